// round 6
// baseline (speedup 1.0000x reference)
#include <cuda_runtime.h>
#include <math.h>

#define NRR 512
#define NAA 512
#define KC 4               // gaussian chunks per tile
#define NTILES 256         // 16x16 tiles of 32x32 px

// Scratch (device globals; no allocs).
__device__ float g_part[KC][NRR * NAA];   // per-chunk partials (exclusive writes)
__device__ int   g_tick[NTILES];          // per-tile tickets (self-resetting)

// One fused kernel. Block = (tile-pair x, tile y, chunk z), 256 threads.
// Warps 0-3 render tile A=(bx,by), warps 4-7 tile B=(bx+8,by); 8 rows/thread.
// Per chunk: cheap cull (trace bound) -> full prep of loose survivors ->
// exact cull + per-tile compaction -> splat -> partials + last-block reduce.
__global__ __launch_bounds__(256) void sar_kernel(
    const float* __restrict__ pos,
    const float* __restrict__ cov,
    const float* __restrict__ inten,
    float* __restrict__ out, int N)
{
    __shared__ int    sLoose[256];
    __shared__ float4 sA0[256], sA1[256];   // (rc,cc,A,B), (C,w,-,-)
    __shared__ float4 sB0[256], sB1[256];
    __shared__ int    warpL[8],  warpLoff[8];
    __shared__ int    warpA[8],  warpAoff[8];
    __shared__ int    warpB[8],  warpBoff[8];
    __shared__ int    sMl, sMA, sMB, sLastA, sLastB;

    const int tid  = threadIdx.x;
    const int lane = tid & 31;
    const int wid  = tid >> 5;
    const int half = tid >> 7;          // 0 = tile A, 1 = tile B
    const int htid = tid & 127;
    const int tx   = htid & 31;
    const int tyg  = htid >> 5;         // 0..3; rows tyg + 4k, k=0..7

    const int bx = blockIdx.x;          // 0..7 (tile pair)
    const int by = blockIdx.y;          // 0..15
    const int chunk = blockIdx.z;
    const int cbeg = (chunk * N) / KC;
    const int cend = ((chunk + 1) * N) / KC;

    const int   rowb = by * 32;
    const float r0f  = (float)rowb;
    const float cA0f = (float)(bx * 32);
    const float cB0f = (float)((bx + 8) * 32);
    const int   col  = (bx + half * 8) * 32 + tx;
    const float colf = (float)col;
    const float rf0  = (float)(rowb + tyg);

    const float cbeta = 0.8660254037844387f;
    const float sbeta = 0.5f;
    const float RCc   = 5773.502691896258f;
    const float RPY   = -2886.7513459481287f;
    const float RPZ   = 5000.0f;
    const float L2E   = 1.4426950408889634f;
    const float T     = 210.0f;   // fp32 exp underflow threshold (matches ref)

    float acc[8];
    #pragma unroll
    for (int k = 0; k < 8; k++) acc[k] = 0.f;

    const unsigned lmask = (1u << lane) - 1u;

    for (int base = cbeg; base < cend; base += 256) {
        // ---- stage 1: cheap cull (pos + cov diagonal; trace bound) ----
        const int n = base + tid;
        bool okL = false;
        if (n < cend) {
            float dx = pos[n*3+0];
            float dy = pos[n*3+1] - RPY;
            float dz = pos[n*3+2] - RPZ;
            float Yr = -cbeta*dy - sbeta*dz;
            float Zr =  sbeta*dy - cbeta*dz;
            float Rmin = sqrtf(Yr*Yr + Zr*Zr + 1e-12f);
            float rc = Rmin + 256.0f - RCc;
            float cc = dx + 256.0f;
            float tr = cov[n*9+0] + cov[n*9+4] + cov[n*9+8] + 1e-4f;
            float bd = sqrtf(T * tr);     // >= er and >= ec (PSD: a,d2 <= trace)
            bool okRow = (rc + bd >= r0f) && (rc - bd <= r0f + 31.0f);
            bool okA = okRow && (cc + bd >= cA0f) && (cc - bd <= cA0f + 31.0f);
            bool okB = okRow && (cc + bd >= cB0f) && (cc - bd <= cB0f + 31.0f);
            okL = okA || okB;
        }
        unsigned balL = __ballot_sync(0xffffffffu, okL);
        if (lane == 0) warpL[wid] = __popc(balL);
        __syncthreads();
        if (tid == 0) {
            int s = 0;
            #pragma unroll
            for (int w2 = 0; w2 < 8; w2++) { warpLoff[w2] = s; s += warpL[w2]; }
            sMl = s;
        }
        __syncthreads();
        if (okL) sLoose[warpLoff[wid] + __popc(balL & lmask)] = n;
        __syncthreads();

        // ---- stage 2: full prep of loose survivors only ----
        const int Ml = sMl;
        bool okA = false, okB = false;
        float rc=0.f, cc=0.f, A=0.f, B=0.f, C=0.f, w=0.f;
        if (tid < Ml) {
            const int g = sLoose[tid];
            float dx = pos[g*3+0];
            float dy = pos[g*3+1] - RPY;
            float dz = pos[g*3+2] - RPZ;
            float Yr = -cbeta*dy - sbeta*dz;
            float Zr =  sbeta*dy - cbeta*dz;
            float Rmin = sqrtf(Yr*Yr + Zr*Zr + 1e-12f);
            rc = Rmin + 256.0f - RCc;
            cc = dx + 256.0f;
            float u1 = Yr / Rmin;
            float u2 = Zr / Rmin;

            const float* S = cov + g*9;
            float S00=S[0], S01=S[1], S02=S[2], S11=S[4], S12=S[5], S22=S[8];

            float c10 = -cbeta*S01 - sbeta*S02;
            float c20 =  sbeta*S01 - cbeta*S02;
            float c11 = cbeta*cbeta*S11 + 2.0f*cbeta*sbeta*S12 + sbeta*sbeta*S22;
            float c12 = cbeta*sbeta*(S22 - S11) + (cbeta*cbeta - sbeta*sbeta)*S12;
            float c22 = sbeta*sbeta*S11 - 2.0f*sbeta*cbeta*S12 + cbeta*cbeta*S22;

            float a  = u1*u1*c11 + 2.0f*u1*u2*c12 + u2*u2*c22 + 1e-4f;
            float b  = u1*c10 + u2*c20;
            float d2 = S00 + 1e-4f;

            float det = a*d2 - b*b;
            float inv = 1.0f / det;
            A = -0.5f * L2E * d2 * inv;
            B =         L2E * b  * inv;
            C = -0.5f * L2E * a  * inv;
            w = inten[g] * 0.15915494309189535f * inv;

            float er = sqrtf(T * a);
            float ec = sqrtf(T * d2);

            bool okRow = (rc + er >= r0f) && (rc - er <= r0f + 31.0f);
            okA = okRow && (cc + ec >= cA0f) && (cc - ec <= cA0f + 31.0f);
            okB = okRow && (cc + ec >= cB0f) && (cc - ec <= cB0f + 31.0f);
        }

        // ---- stage 3: per-tile exact compaction (deterministic order) ----
        unsigned balA = __ballot_sync(0xffffffffu, okA);
        unsigned balB = __ballot_sync(0xffffffffu, okB);
        if (lane == 0) { warpA[wid] = __popc(balA); warpB[wid] = __popc(balB); }
        __syncthreads();
        if (tid == 0) {
            int sa = 0, sb = 0;
            #pragma unroll
            for (int w2 = 0; w2 < 8; w2++) {
                warpAoff[w2] = sa; sa += warpA[w2];
                warpBoff[w2] = sb; sb += warpB[w2];
            }
            sMA = sa; sMB = sb;
        }
        __syncthreads();
        if (okA) {
            int o = warpAoff[wid] + __popc(balA & lmask);
            sA0[o] = make_float4(rc, cc, A, B);
            sA1[o] = make_float4(C, w, 0.f, 0.f);
        }
        if (okB) {
            int o = warpBoff[wid] + __popc(balB & lmask);
            sB0[o] = make_float4(rc, cc, A, B);
            sB1[o] = make_float4(C, w, 0.f, 0.f);
        }
        __syncthreads();

        // ---- splat: 8 rows per thread, own half's tile ----
        const float4* p0s = half ? sB0 : sA0;
        const float4* p1s = half ? sB1 : sA1;
        const int M = half ? sMB : sMA;
        for (int i = 0; i < M; i++) {
            const float4 p0 = p0s[i];     // uniform -> broadcast LDS
            const float4 p1 = p1s[i];
            float dc  = colf - p0.y;
            float Bdc = p0.w * dc;
            float Cq  = p1.x * dc * dc;
            float drb = rf0 - p0.x;
            #pragma unroll
            for (int k = 0; k < 8; k++) {
                float dr = drb + (float)(4 * k);
                float t  = fmaf(p0.z, dr, Bdc);
                float m  = fmaf(t, dr, Cq);
                float e;
                asm("ex2.approx.ftz.f32 %0, %1;" : "=f"(e) : "f"(m));
                acc[k] = fmaf(p1.y, e, acc[k]);
            }
        }
        __syncthreads();   // smem reuse for next chunk
    }

    // ---- partial write ----
    float* dst = g_part[chunk];
    int idx[8];
    #pragma unroll
    for (int k = 0; k < 8; k++) {
        idx[k] = (rowb + tyg + 4*k) * NAA + col;
        dst[idx[k]] = acc[k];
    }

    // ---- last chunk-block per tile reduces (fixed order -> deterministic) ----
    const int tA = by * 16 + bx;
    const int tB = by * 16 + bx + 8;
    __threadfence();
    __syncthreads();
    if (tid == 0)   sLastA = (atomicAdd(&g_tick[tA], 1) == KC - 1) ? 1 : 0;
    if (tid == 128) sLastB = (atomicAdd(&g_tick[tB], 1) == KC - 1) ? 1 : 0;
    __syncthreads();
    const int last = half ? sLastB : sLastA;
    if (last) {
        #pragma unroll
        for (int k = 0; k < 8; k++) {
            int i = idx[k];
            out[i] = (g_part[0][i] + g_part[1][i]) + (g_part[2][i] + g_part[3][i]);
        }
    }
    if (tid == 0   && sLastA) g_tick[tA] = 0;   // self-reset for graph replay
    if (tid == 128 && sLastB) g_tick[tB] = 0;
}

extern "C" void kernel_launch(void* const* d_in, const int* in_sizes, int n_in,
                              void* d_out, int out_size)
{
    const float* pos   = (const float*)d_in[0];
    const float* cov   = (const float*)d_in[1];
    const float* inten = (const float*)d_in[2];
    float* out = (float*)d_out;

    int N = in_sizes[2];   // N_GAUSS

    dim3 grd(8, 16, KC);   // tile-pairs x, tiles y, chunks
    sar_kernel<<<grd, 256>>>(pos, cov, inten, out, N);
}